// round 16
// baseline (speedup 1.0000x reference)
#include <cuda_runtime.h>
#include <math.h>

#define N_NODES 50000
#define N_EDGES 800000
#define HD 192

#define ASTR 68          // padded smem A-row stride (floats), 16B-aligned, bank-friendly
#define NSLOT 320        // k-slots in smem A buffer
#define BSTR 196         // padded smem B-row stride (floats)
#define SMEM_BYTES ((NSLOT*ASTR + 16*BSTR)*4)

// persistent scratch (aggregation buffers) — re-initialized every launch
__device__ float g_sum[N_NODES*128];
__device__ int   g_max[N_NODES*128];

#define MAX_INIT ((int)0x807fffffu)   // encode(-inf)

__device__ __forceinline__ int enc_f(float f){
    int i = __float_as_int(f);
    return i >= 0 ? i : (i ^ 0x7fffffff);
}
__device__ __forceinline__ float dec_f(int m){
    if (m == MAX_INIT) return 0.0f;   // empty mailbox -> 0 (matches reference isfinite fix)
    int b = m >= 0 ? m : (m ^ 0x7fffffff);
    return __int_as_float(b);
}

__global__ void init_agg_kernel(){
    int t = blockIdx.x * 256 + threadIdx.x;
    if (t < N_NODES*128){ g_sum[t] = 0.0f; g_max[t] = MAX_INIT; }
}

// m = [node_feats[src] (64) | update_edges (64)] scattered to dst by sum & max
__global__ void __launch_bounds__(256) scatter_kernel(
    const float* __restrict__ nf, const int* __restrict__ src,
    const int* __restrict__ dst, const float* __restrict__ upd_e)
{
    int t = blockIdx.x * 256 + threadIdx.x;
    int e = t >> 7, j = t & 127;
    if (e >= N_EDGES) return;
    int d = dst[e];
    float v = (j < 64) ? nf[src[e]*64 + j] : upd_e[e*64 + (j-64)];
    atomicAdd(&g_sum[d*128 + j], v);
    atomicMax(&g_max[d*128 + j], enc_f(v));
}

// Generic GEMM stage: C[64 rows][192 cols] += A(slots in smem) * B(loaded via bload)
// thread (tx,ty): rows ty*4+0..3, cols tx*12+0..11
template<class BL, class AS>
__device__ __forceinline__ void gemm_core(int KD, float* Ast, float* Bs,
                                          float (&acc)[4][12], int tid, int tx, int ty,
                                          BL bload, AS aslot)
{
    for (int k0 = 0; k0 < KD; k0 += 16) {
        __syncthreads();
        #pragma unroll
        for (int i = 0; i < 12; ++i) {           // 16*192 = 12*256
            int idx = tid + i*256;
            int j = idx >> 4, bk = idx & 15;
            Bs[bk*BSTR + j] = bload(k0 + bk, j);
        }
        __syncthreads();
        #pragma unroll
        for (int kk = 0; kk < 16; ++kk) {
            int slot = aslot(k0 + kk);
            float4 a4 = *(const float4*)&Ast[slot*ASTR + ty*4];
            const float* bp = &Bs[kk*BSTR + tx*12];
            float4 b0 = *(const float4*)(bp);
            float4 b1 = *(const float4*)(bp+4);
            float4 b2 = *(const float4*)(bp+8);
            float av[4] = {a4.x,a4.y,a4.z,a4.w};
            float bv[12] = {b0.x,b0.y,b0.z,b0.w,b1.x,b1.y,b1.z,b1.w,b2.x,b2.y,b2.z,b2.w};
            #pragma unroll
            for (int r = 0; r < 4; ++r)
                #pragma unroll
                for (int c = 0; c < 12; ++c)
                    acc[r][c] = fmaf(av[r], bv[c], acc[r][c]);
        }
    }
}

// Fully fused path kernel:
//   stage1: A(K1) @ W1^T + b1 -> LayerNorm -> LeakyReLU(0.2)      (booster L1)
//   stage2: @ W2^T + b2                                           (booster L2)
//   stage3: s = x@Wih^T + h@Whh^T + bih + bhh  (K=256 concat)     (GRU gates sum)
//   stage3b: hn = h@Whh_n^T ; res = h@Wr^T                        (small GEMMs)
//   combine: GRU + residual + LeakyReLU(0.01) -> out[gm*64+j]
// smem slot plan: stage inputs live at slots 0..K1-1, h feats at 256..319,
// each stage writes its 192-wide output back to slots 0..191.
template<int K1, bool IS_EDGE>
__global__ void __launch_bounds__(256, 2)
fused_path_kernel(const float* __restrict__ nf, const float* __restrict__ ef,
                  const int* __restrict__ src, const int* __restrict__ dst,
                  const float* __restrict__ W1, const float* __restrict__ b1,
                  const float* __restrict__ lng, const float* __restrict__ lnb,
                  const float* __restrict__ W2, const float* __restrict__ b2,
                  const float* __restrict__ Wih, const float* __restrict__ Whh,
                  const float* __restrict__ bih, const float* __restrict__ bhh,
                  const float* __restrict__ Wr,  const float* __restrict__ br,
                  float* __restrict__ outp, int rows)
{
    extern __shared__ float sm[];
    float* Ast = sm;                       // [NSLOT][ASTR]
    float* Bs  = sm + NSLOT*ASTR;          // [16][BSTR]
    int tid = threadIdx.x, tx = tid & 15, ty = tid >> 4;
    int m0 = blockIdx.x * 64;

    // ---- gather stage-1 input into slots 0..K1-1, h feats into 256..319 ----
    if (IS_EDGE) {
        // msg = [nf[src] | nf[dst] | ef]
        for (int idx = tid; idx < 64*192; idx += 256) {
            int m = idx / 192, k = idx % 192;
            int e = min(m0 + m, rows - 1);
            float v;
            if (k < 64)        v = nf[src[e]*64 + k];
            else if (k < 128)  v = nf[dst[e]*64 + (k-64)];
            else               v = ef[e*64 + (k-128)];
            Ast[k*ASTR + m] = v;
        }
        for (int idx = tid; idx < 64*64; idx += 256) {
            int m = idx >> 6, k = idx & 63;
            int e = min(m0 + m, rows - 1);
            Ast[(256+k)*ASTR + m] = ef[e*64 + k];
        }
    } else {
        // agg = [sum(128) | max(128)]
        for (int idx = tid; idx < 64*256; idx += 256) {
            int m = idx >> 8, k = idx & 255;
            int n = min(m0 + m, rows - 1);
            float v = (k < 128) ? g_sum[n*128 + k] : dec_f(g_max[n*128 + (k-128)]);
            Ast[k*ASTR + m] = v;
        }
        for (int idx = tid; idx < 64*64; idx += 256) {
            int m = idx >> 6, k = idx & 63;
            int n = min(m0 + m, rows - 1);
            Ast[(256+k)*ASTR + m] = nf[n*64 + k];
        }
    }

    float acc[4][12];

    // ---------------- stage 1: W1 + bias + LayerNorm + LeakyReLU(0.2) ----------------
    #pragma unroll
    for (int r = 0; r < 4; ++r)
        #pragma unroll
        for (int c = 0; c < 12; ++c) acc[r][c] = 0.f;

    gemm_core(K1, Ast, Bs, acc, tid, tx, ty,
        [&](int k, int j){ return W1[j*K1 + k]; },
        [&](int k){ return k; });

    #pragma unroll
    for (int r = 0; r < 4; ++r){
        float s = 0.f, q = 0.f;
        #pragma unroll
        for (int c = 0; c < 12; ++c){
            float v = acc[r][c] + b1[tx*12+c];
            acc[r][c] = v; s += v; q += v*v;
        }
        #pragma unroll
        for (int o = 8; o; o >>= 1){
            s += __shfl_xor_sync(0xffffffffu, s, o, 16);
            q += __shfl_xor_sync(0xffffffffu, q, o, 16);
        }
        float mu = s * (1.0f/HD);
        float var = q * (1.0f/HD) - mu*mu;
        float rstd = rsqrtf(var + 1e-5f);
        #pragma unroll
        for (int c = 0; c < 12; ++c){
            int j = tx*12+c;
            float v = (acc[r][c] - mu) * rstd * lng[j] + lnb[j];
            acc[r][c] = v > 0.f ? v : 0.2f*v;
        }
    }
    __syncthreads();
    #pragma unroll
    for (int r = 0; r < 4; ++r)
        #pragma unroll
        for (int c = 0; c < 12; ++c)
            Ast[(tx*12+c)*ASTR + ty*4 + r] = acc[r][c];

    // ---------------- stage 2: W2 + b2 ----------------
    #pragma unroll
    for (int r = 0; r < 4; ++r)
        #pragma unroll
        for (int c = 0; c < 12; ++c) acc[r][c] = 0.f;

    gemm_core(HD, Ast, Bs, acc, tid, tx, ty,
        [&](int k, int j){ return W2[j*HD + k]; },
        [&](int k){ return k; });

    #pragma unroll
    for (int r = 0; r < 4; ++r)
        #pragma unroll
        for (int c = 0; c < 12; ++c) acc[r][c] += b2[tx*12+c];
    __syncthreads();
    #pragma unroll
    for (int r = 0; r < 4; ++r)
        #pragma unroll
        for (int c = 0; c < 12; ++c)
            Ast[(tx*12+c)*ASTR + ty*4 + r] = acc[r][c];

    // ---------------- stage 3: s = x@Wih^T + h@Whh^T + biases (K=256 concat) ----------------
    #pragma unroll
    for (int r = 0; r < 4; ++r)
        #pragma unroll
        for (int c = 0; c < 12; ++c) acc[r][c] = 0.f;

    gemm_core(256, Ast, Bs, acc, tid, tx, ty,
        [&](int k, int j){ return (k < HD) ? Wih[j*HD + k] : Whh[j*64 + (k-HD)]; },
        [&](int k){ return (k < HD) ? k : k + 64; });

    #pragma unroll
    for (int r = 0; r < 4; ++r)
        #pragma unroll
        for (int c = 0; c < 12; ++c){
            int j = tx*12+c;
            acc[r][c] += bih[j] + bhh[j];
        }
    __syncthreads();
    #pragma unroll
    for (int r = 0; r < 4; ++r)
        #pragma unroll
        for (int c = 0; c < 12; ++c)
            Ast[(tx*12+c)*ASTR + ty*4 + r] = acc[r][c];

    // ---------------- stage 3b: hn (Whh rows 128..191) and res (Wr), K=64 ----------------
    float ahn[4][4], ars[4][4];
    #pragma unroll
    for (int r = 0; r < 4; ++r)
        #pragma unroll
        for (int c = 0; c < 4; ++c){ ahn[r][c] = 0.f; ars[r][c] = 0.f; }

    for (int k0 = 0; k0 < 64; k0 += 16) {
        __syncthreads();
        #pragma unroll
        for (int i = 0; i < 8; ++i) {        // 16*128 = 8*256
            int idx = tid + i*256;
            int c = idx >> 4, bk = idx & 15;
            Bs[bk*132 + c] = (c < 64) ? Whh[(128+c)*64 + k0+bk]
                                      : Wr[(c-64)*64 + k0+bk];
        }
        __syncthreads();
        #pragma unroll
        for (int kk = 0; kk < 16; ++kk) {
            float4 a4 = *(const float4*)&Ast[(256+k0+kk)*ASTR + ty*4];
            float4 bh = *(const float4*)&Bs[kk*132 + tx*4];
            float4 bw = *(const float4*)&Bs[kk*132 + 64 + tx*4];
            float av[4]  = {a4.x,a4.y,a4.z,a4.w};
            float bhv[4] = {bh.x,bh.y,bh.z,bh.w};
            float bwv[4] = {bw.x,bw.y,bw.z,bw.w};
            #pragma unroll
            for (int r = 0; r < 4; ++r)
                #pragma unroll
                for (int c = 0; c < 4; ++c){
                    ahn[r][c] = fmaf(av[r], bhv[c], ahn[r][c]);
                    ars[r][c] = fmaf(av[r], bwv[c], ars[r][c]);
                }
        }
    }

    // ---------------- combine: GRU + residual + LeakyReLU(0.01) ----------------
    #pragma unroll
    for (int r = 0; r < 4; ++r){
        int mm = ty*4 + r;
        int gm = m0 + mm;
        if (gm < rows) {
            float ov[4];
            #pragma unroll
            for (int c = 0; c < 4; ++c){
                int j = tx*4 + c;
                float sr = Ast[j*ASTR + mm];
                float sz = Ast[(64+j)*ASTR + mm];
                float sn = Ast[(128+j)*ASTR + mm];
                float hv = Ast[(256+j)*ASTR + mm];
                float hn = ahn[r][c] + bhh[128+j];
                float rr = 1.0f / (1.0f + expf(-sr));
                float zz = 1.0f / (1.0f + expf(-sz));
                float nn = tanhf(sn + (rr - 1.0f)*hn);
                float o  = (1.0f - zz)*nn + zz*hv + ars[r][c] + br[j];
                ov[c] = o > 0.f ? o : 0.01f*o;
            }
            *(float4*)&outp[gm*64 + tx*4] = make_float4(ov[0], ov[1], ov[2], ov[3]);
        }
    }
}

extern "C" void kernel_launch(void* const* d_in, const int* in_sizes, int n_in,
                              void* d_out, int out_size)
{
    const float* nf    = (const float*)d_in[0];
    const float* ef    = (const float*)d_in[1];
    const int*   src   = (const int*)  d_in[2];
    const int*   dst   = (const int*)  d_in[3];
    const float* W1e   = (const float*)d_in[4];
    const float* W1n   = (const float*)d_in[5];
    const float* b1    = (const float*)d_in[6];
    const float* lng   = (const float*)d_in[7];
    const float* lnb   = (const float*)d_in[8];
    const float* W2    = (const float*)d_in[9];
    const float* b2    = (const float*)d_in[10];
    const float* Wih_e = (const float*)d_in[11];
    const float* Whh_e = (const float*)d_in[12];
    const float* bih_e = (const float*)d_in[13];
    const float* bhh_e = (const float*)d_in[14];
    const float* Wih_a = (const float*)d_in[15];
    const float* Whh_a = (const float*)d_in[16];
    const float* bih_a = (const float*)d_in[17];
    const float* bhh_a = (const float*)d_in[18];
    const float* Wre   = (const float*)d_in[19];
    const float* bre   = (const float*)d_in[20];
    const float* Wra   = (const float*)d_in[21];
    const float* bra   = (const float*)d_in[22];

    float* out_nodes = (float*)d_out;                       // [N, 64]
    float* out_edges = (float*)d_out + (size_t)N_NODES*64;  // [E, 64]

    cudaFuncSetAttribute(fused_path_kernel<192, true>,
                         cudaFuncAttributeMaxDynamicSharedMemorySize, SMEM_BYTES);
    cudaFuncSetAttribute(fused_path_kernel<256, false>,
                         cudaFuncAttributeMaxDynamicSharedMemorySize, SMEM_BYTES);

    // 1) init aggregation buffers (every launch — graph replays)
    init_agg_kernel<<<(N_NODES*128 + 255)/256, 256>>>();

    // 2) edge path: booster + GRU + residual -> update_edges
    fused_path_kernel<192, true><<<N_EDGES/64, 256, SMEM_BYTES>>>(
        nf, ef, src, dst, W1e, b1, lng, lnb, W2, b2,
        Wih_e, Whh_e, bih_e, bhh_e, Wre, bre, out_edges, N_EDGES);

    // 3) aggregation: sum & max of m = [h_src | update_edges] at dst
    scatter_kernel<<<(N_EDGES*128)/256, 256>>>(nf, src, dst, out_edges);

    // 4) node path -> update_nodes
    fused_path_kernel<256, false><<<(N_NODES + 63)/64, 256, SMEM_BYTES>>>(
        nf, ef, src, dst, W1n, b1, lng, lnb, W2, b2,
        Wih_a, Whh_a, bih_a, bhh_a, Wra, bra, out_nodes, N_NODES);
}